// round 2
// baseline (speedup 1.0000x reference)
#include <cuda_runtime.h>
#include <math.h>

#define NTOK   49
#define HEADS  6
#define DIM    192
#define DH     32
#define QSCALE 0.1767766952966369f   /* 32^-0.5 */

/* shared memory layout (float offsets) */
#define OFF_SX   0        /* 49*192 = 9408 floats; reused as attention-out */
#define OFF_SQ   9408     /* q  [h][n][d]           : 9408 */
#define OFF_SKT  18816    /* kT [h][d][n pad 52]    : 6*32*52 = 9984 */
#define OFF_SV   28800    /* v  [h][n][d] + 96 pad  : 9504 */
#define OFF_SWT  38304    /* weight chunk T [k][64 pad 65] : 192*65 = 12480 */
#define OFF_SP   50784    /* per-warp probs [8][7][52] : 2912 */
#define OFF_STAB 53696    /* bias table 169*6 -> pad 1016 */
#define OFF_SREL 54712    /* rel idx 2401 ints */
#define SMEM_FLOATS (54712 + 2401)
#define SMEM_BYTES  (SMEM_FLOATS * 4)   /* 228,452 B */

__global__ __launch_bounds__(256, 1)
void win_attn_fused(const float* __restrict__ x,
                    const float* __restrict__ qkv_w,
                    const float* __restrict__ qkv_b,
                    const float* __restrict__ proj_w,
                    const float* __restrict__ proj_b,
                    const float* __restrict__ bias_table,
                    const int*   __restrict__ rel_idx,
                    float* __restrict__ out)
{
    extern __shared__ float smem[];
    float* sx   = smem + OFF_SX;
    float* sq   = smem + OFF_SQ;
    float* skT  = smem + OFF_SKT;
    float* sv   = smem + OFF_SV;
    float* swT  = smem + OFF_SWT;
    float* sp   = smem + OFF_SP;
    float* stab = smem + OFF_STAB;
    int*   srel = (int*)(smem + OFF_SREL);

    const int tid = threadIdx.x;
    const int b   = blockIdx.x;

    /* ---------- phase 0: load x tile, rel idx, bias table ---------- */
    {
        const float4* xg  = (const float4*)(x + (size_t)b * (NTOK * DIM));
        float4*       sx4 = (float4*)sx;
        #pragma unroll 2
        for (int i = tid; i < NTOK * DIM / 4; i += 256) sx4[i] = xg[i];
        for (int i = tid; i < NTOK * NTOK; i += 256) srel[i] = rel_idx[i];
        for (int i = tid; i < 169 * HEADS; i += 256) stab[i] = bias_table[i];
        if (tid < 96) sv[HEADS * NTOK * DH + tid] = 0.0f;  /* v tail pad -> exact 0 */
    }
    __syncthreads();

    const int ct = tid & 63;   /* one output column per thread within a 64-col chunk */
    const int rg = tid >> 6;   /* 4 row groups; rows are rg + 4*i (rg0 gets 13 rows) */

    /* ---------- phase 1: qkv GEMM, 9 chunks of 64 cols ---------- */
    for (int cc = 0; cc < 9; cc++) {
        if (cc) __syncthreads();
        /* load weight chunk transposed: swT[k][c_local], pad 65 (conflict-free both ways) */
        for (int i = tid; i < 64 * DIM; i += 256) {
            int r = i / DIM, kk = i - r * DIM;
            swT[kk * 65 + r] = qkv_w[(cc * 64 + r) * DIM + kk];
        }
        __syncthreads();

        const int   c    = cc * 64 + ct;
        const float bias = qkv_b[c];
        float acc[13];
        #pragma unroll
        for (int i = 0; i < 13; i++) acc[i] = 0.f;

        #pragma unroll 2
        for (int k = 0; k < DIM; k += 2) {
            float w0 = swT[k * 65 + ct];
            float w1 = swT[(k + 1) * 65 + ct];
            #pragma unroll
            for (int i = 0; i < 13; i++) {
                if (i < 12 || rg == 0) {
                    int row = rg + 4 * i;
                    float2 xv = *(const float2*)&sx[row * DIM + k];  /* warp-broadcast */
                    acc[i] = fmaf(xv.x, w0, acc[i]);
                    acc[i] = fmaf(xv.y, w1, acc[i]);
                }
            }
        }

        const int which = c / DIM;
        const int r     = c - which * DIM;
        const int h     = r >> 5;
        const int d     = r & 31;
        #pragma unroll
        for (int i = 0; i < 13; i++) {
            if (i < 12 || rg == 0) {
                int row = rg + 4 * i;
                float v = acc[i] + bias;
                if (which == 0)      sq[(h * NTOK + row) * DH + d]  = v * QSCALE;
                else if (which == 1) skT[(h * DH + d) * 52 + row]   = v;
                else                 sv[(h * NTOK + row) * DH + d]  = v;
            }
        }
    }
    __syncthreads();

    /* ---------- phase 2: attention (42 units = 6 heads x 7 row-blocks over 8 warps) ---------- */
    const int wid  = tid >> 5;
    const int lane = tid & 31;
    float* sout = sx;                      /* reuse x tile for attention output */
    float* spw  = sp + wid * 7 * 52;       /* per-warp prob buffer */

    for (int u = wid; u < 42; u += 8) {
        const int h  = u / 7;
        const int n0 = (u - h * 7) * 7;
        const float* kh = skT + h * DH * 52;
        const float* qh = sq  + h * NTOK * DH;
        const float* vh = sv  + h * NTOK * DH;

        /* scores: lane owns m=lane and m=32+lane (lanes<17) */
        float a0[7], a1[7];
        #pragma unroll
        for (int i = 0; i < 7; i++) { a0[i] = 0.f; a1[i] = 0.f; }

        #pragma unroll 4
        for (int d = 0; d < DH; d++) {
            float k0 = kh[d * 52 + lane];
            float k1 = (lane < 17) ? kh[d * 52 + 32 + lane] : 0.f;
            #pragma unroll
            for (int i = 0; i < 7; i++) {
                float qv = qh[(n0 + i) * DH + d];   /* warp-broadcast */
                a0[i] = fmaf(qv, k0, a0[i]);
                a1[i] = fmaf(qv, k1, a1[i]);
            }
        }

        /* bias + softmax, probs -> smem (rows padded to 52, tail zeroed) */
        #pragma unroll
        for (int i = 0; i < 7; i++) {
            int n = n0 + i;
            float s0 = a0[i] + stab[srel[n * NTOK + lane] * HEADS + h];
            float s1 = -1e30f;
            if (lane < 17) s1 = a1[i] + stab[srel[n * NTOK + 32 + lane] * HEADS + h];
            float mx = fmaxf(s0, s1);
            #pragma unroll
            for (int off = 16; off > 0; off >>= 1)
                mx = fmaxf(mx, __shfl_xor_sync(0xffffffffu, mx, off));
            float e0 = __expf(s0 - mx);
            float e1 = (lane < 17) ? __expf(s1 - mx) : 0.f;
            float sm = e0 + e1;
            #pragma unroll
            for (int off = 16; off > 0; off >>= 1)
                sm += __shfl_xor_sync(0xffffffffu, sm, off);
            float inv = 1.f / sm;
            spw[i * 52 + lane] = e0 * inv;
            if (lane < 20) spw[i * 52 + 32 + lane] = (lane < 17) ? e1 * inv : 0.f;
        }
        __syncwarp();

        /* AV: lane owns d; float4 prob broadcast, padded tail contributes exact 0 */
        float o[7];
        #pragma unroll
        for (int i = 0; i < 7; i++) o[i] = 0.f;
        #pragma unroll 2
        for (int mq = 0; mq < 13; mq++) {
            int mb = mq * 4;
            float v0 = vh[(mb + 0) * DH + lane];
            float v1 = vh[(mb + 1) * DH + lane];
            float v2 = vh[(mb + 2) * DH + lane];
            float v3 = vh[(mb + 3) * DH + lane];
            #pragma unroll
            for (int i = 0; i < 7; i++) {
                float4 p = *(const float4*)&spw[i * 52 + mb];
                o[i] = fmaf(p.x, v0, o[i]);
                o[i] = fmaf(p.y, v1, o[i]);
                o[i] = fmaf(p.z, v2, o[i]);
                o[i] = fmaf(p.w, v3, o[i]);
            }
        }
        #pragma unroll
        for (int i = 0; i < 7; i++)
            sout[(n0 + i) * DIM + h * DH + lane] = o[i];
        __syncwarp();
    }

    /* ---------- phase 3: proj GEMM, 3 chunks of 64 cols, store to gmem ---------- */
    float* outg = out + (size_t)b * (NTOK * DIM);
    for (int cc = 0; cc < 3; cc++) {
        __syncthreads();
        for (int i = tid; i < 64 * DIM; i += 256) {
            int r = i / DIM, kk = i - r * DIM;
            swT[kk * 65 + r] = proj_w[(cc * 64 + r) * DIM + kk];
        }
        __syncthreads();

        const int   c    = cc * 64 + ct;
        const float bias = proj_b[c];
        float acc[13];
        #pragma unroll
        for (int i = 0; i < 13; i++) acc[i] = 0.f;

        #pragma unroll 2
        for (int k = 0; k < DIM; k += 2) {
            float w0 = swT[k * 65 + ct];
            float w1 = swT[(k + 1) * 65 + ct];
            #pragma unroll
            for (int i = 0; i < 13; i++) {
                if (i < 12 || rg == 0) {
                    int row = rg + 4 * i;
                    float2 xv = *(const float2*)&sout[row * DIM + k];
                    acc[i] = fmaf(xv.x, w0, acc[i]);
                    acc[i] = fmaf(xv.y, w1, acc[i]);
                }
            }
        }

        #pragma unroll
        for (int i = 0; i < 13; i++) {
            if (i < 12 || rg == 0) {
                int row = rg + 4 * i;
                outg[row * DIM + c] = acc[i] + bias;
            }
        }
    }
}

extern "C" void kernel_launch(void* const* d_in, const int* in_sizes, int n_in,
                              void* d_out, int out_size)
{
    const float* x          = (const float*)d_in[0];
    const float* qkv_w      = (const float*)d_in[1];
    const float* qkv_b      = (const float*)d_in[2];
    const float* proj_w     = (const float*)d_in[3];
    const float* proj_b     = (const float*)d_in[4];
    const float* bias_table = (const float*)d_in[5];
    const int*   rel_idx    = (const int*)d_in[6];
    float*       out        = (float*)d_out;

    const int nB = in_sizes[0] / (NTOK * DIM);   /* 4096 windows */

    cudaFuncSetAttribute(win_attn_fused,
                         cudaFuncAttributeMaxDynamicSharedMemorySize, SMEM_BYTES);
    win_attn_fused<<<nB, 256, SMEM_BYTES>>>(x, qkv_w, qkv_b, proj_w, proj_b,
                                            bias_table, rel_idx, out);
}

// round 4
// speedup vs baseline: 2.8591x; 2.8591x over previous
#include <cuda_runtime.h>
#include <cuda_bf16.h>
#include <cstdint>
#include <math.h>

#define NTOK   49
#define HEADS  6
#define DIM    192
#define DH     32
#define QSCALE 0.1767766952966369f

/* ================= device scratch (static: allocation-free) ================= */
__device__ float          g_qkv [200704u * 576u];   /* 462 MB qkv intermediate  */
__device__ float          g_attn[200704u * 192u];   /* 154 MB attention output  */
__device__ __nv_bfloat16  g_wqh[576 * 192], g_wql[576 * 192];
__device__ __nv_bfloat16  g_wph[192 * 192], g_wpl[192 * 192];
__device__ float          g_bias[HEADS * NTOK * NTOK];

__device__ __forceinline__ uint32_t pack_bf2(float a, float b) {
    __nv_bfloat16 ha = __float2bfloat16(a), hb = __float2bfloat16(b);
    return (uint32_t)__bfloat16_as_ushort(ha) | ((uint32_t)__bfloat16_as_ushort(hb) << 16);
}

/* ================= prep: split weights to bf16 hi/lo, materialize bias ================= */
__global__ void prep_kernel(const float* __restrict__ qkv_w, const float* __restrict__ proj_w,
                            const float* __restrict__ bias_table, const int* __restrict__ rel_idx)
{
    int i = blockIdx.x * 256 + threadIdx.x;
    if (i < 576 * 192) {
        float w = qkv_w[i];
        __nv_bfloat16 h = __float2bfloat16(w);
        g_wqh[i] = h;
        g_wql[i] = __float2bfloat16(w - __bfloat162float(h));
    }
    if (i < 192 * 192) {
        float w = proj_w[i];
        __nv_bfloat16 h = __float2bfloat16(w);
        g_wph[i] = h;
        g_wpl[i] = __float2bfloat16(w - __bfloat162float(h));
    }
    if (i < HEADS * NTOK * NTOK) {
        int m = i % NTOK, t = i / NTOK;
        int n = t % NTOK, h = t / NTOK;
        g_bias[i] = bias_table[rel_idx[n * NTOK + m] * HEADS + h];
    }
}

/* ================= mma.sync bf16 m16n8k16 ================= */
__device__ __forceinline__ void mma16816(float* c, const uint32_t* a, const uint32_t* b) {
    asm volatile(
        "mma.sync.aligned.m16n8k16.row.col.f32.bf16.bf16.f32 "
        "{%0,%1,%2,%3}, {%4,%5,%6,%7}, {%8,%9}, {%0,%1,%2,%3};"
        : "+f"(c[0]), "+f"(c[1]), "+f"(c[2]), "+f"(c[3])
        : "r"(a[0]), "r"(a[1]), "r"(a[2]), "r"(a[3]), "r"(b[0]), "r"(b[1]));
}

/* GEMM: C[Mrows, ldc] section = A(fp32, lda=192) x B^T, B=[Nrows,192] bf16 hi/lo.
   CTA tile 128(M) x 192(N), 8 warps (4x2), warp tile 32x96, K chunks of 64.
   3-term split: AhBh + AhBl + AlBh. smem rows padded to 72 bf16 (144 B). */
#define SM_AH 0
#define SM_AL 18432
#define SM_BH 36864
#define SM_BL 64512
#define GEMM_SMEM 92160

__global__ __launch_bounds__(256, 1)
void gemm_bf16x3(const float* __restrict__ A,
                 const __nv_bfloat16* __restrict__ Bhi,
                 const __nv_bfloat16* __restrict__ Blo,
                 const float* __restrict__ bias,
                 float* __restrict__ C, int ldc)
{
    extern __shared__ char smc[];
    const int tid = threadIdx.x, wid = tid >> 5, lane = tid & 31;
    const int mtile = blockIdx.x, ntile = blockIdx.y;

    const int wm = (wid & 3) * 32;        /* warp M offset in tile */
    const int wn = (wid >> 2) * 96;       /* warp N offset in tile */

    const float* Abase = A + (size_t)mtile * 128 * 192;
    const __nv_bfloat16* Bhb = Bhi + (size_t)ntile * 192 * 192;
    const __nv_bfloat16* Blb = Blo + (size_t)ntile * 192 * 192;

    float acc[2][12][4];
    #pragma unroll
    for (int mf = 0; mf < 2; mf++)
        #pragma unroll
        for (int nf = 0; nf < 12; nf++)
            #pragma unroll
            for (int j = 0; j < 4; j++) acc[mf][nf][j] = 0.f;

    for (int kc = 0; kc < 3; kc++) {
        if (kc) __syncthreads();

        /* --- A chunk 128x64 fp32 -> hi/lo bf16 into smem (pad 72) --- */
        #pragma unroll
        for (int it = 0; it < 8; it++) {
            int g   = tid + it * 256;          /* 2048 float4 groups */
            int row = g >> 4, c4 = (g & 15) << 2;
            float4 f = *(const float4*)(Abase + row * 192 + kc * 64 + c4);
            uint32_t h0 = pack_bf2(f.x, f.y), h1 = pack_bf2(f.z, f.w);
            float rx = f.x - __bfloat162float(__ushort_as_bfloat16((unsigned short)h0));
            float ry = f.y - __bfloat162float(__ushort_as_bfloat16((unsigned short)(h0 >> 16)));
            float rz = f.z - __bfloat162float(__ushort_as_bfloat16((unsigned short)h1));
            float rw = f.w - __bfloat162float(__ushort_as_bfloat16((unsigned short)(h1 >> 16)));
            uint32_t l0 = pack_bf2(rx, ry), l1 = pack_bf2(rz, rw);
            *(uint2*)(smc + SM_AH + row * 144 + c4 * 2) = make_uint2(h0, h1);
            *(uint2*)(smc + SM_AL + row * 144 + c4 * 2) = make_uint2(l0, l1);
        }
        /* --- B chunk 192x64 bf16 (pre-split) into smem (pad 72) --- */
        #pragma unroll
        for (int it = 0; it < 6; it++) {
            int g   = tid + it * 256;          /* 1536 groups of 8 bf16 */
            int row = g >> 3, c8 = (g & 7) << 3;
            uint4 u = *(const uint4*)(Bhb + row * 192 + kc * 64 + c8);
            uint4 w = *(const uint4*)(Blb + row * 192 + kc * 64 + c8);
            *(uint4*)(smc + SM_BH + row * 144 + c8 * 2) = u;
            *(uint4*)(smc + SM_BL + row * 144 + c8 * 2) = w;
        }
        __syncthreads();

        #pragma unroll
        for (int ks = 0; ks < 4; ks++) {
            const int kk = ks * 16 + (lane & 3) * 2;

            uint32_t ah[2][4], al[2][4];
            #pragma unroll
            for (int mf = 0; mf < 2; mf++)
                #pragma unroll
                for (int rgi = 0; rgi < 4; rgi++) {
                    int rr = wm + mf * 16 + (lane >> 2) + (rgi & 1) * 8;
                    int kx = kk + (rgi >> 1) * 8;
                    ah[mf][rgi] = *(const uint32_t*)(smc + SM_AH + rr * 144 + kx * 2);
                    al[mf][rgi] = *(const uint32_t*)(smc + SM_AL + rr * 144 + kx * 2);
                }

            uint32_t bh[12][2], bl[12][2];
            #pragma unroll
            for (int nf = 0; nf < 12; nf++) {
                int n = wn + nf * 8 + (lane >> 2);
                bh[nf][0] = *(const uint32_t*)(smc + SM_BH + n * 144 + kk * 2);
                bh[nf][1] = *(const uint32_t*)(smc + SM_BH + n * 144 + (kk + 8) * 2);
                bl[nf][0] = *(const uint32_t*)(smc + SM_BL + n * 144 + kk * 2);
                bl[nf][1] = *(const uint32_t*)(smc + SM_BL + n * 144 + (kk + 8) * 2);
            }

            #pragma unroll
            for (int mf = 0; mf < 2; mf++)
                #pragma unroll
                for (int nf = 0; nf < 12; nf++) {
                    mma16816(acc[mf][nf], ah[mf], bh[nf]);
                    mma16816(acc[mf][nf], ah[mf], bl[nf]);
                    mma16816(acc[mf][nf], al[mf], bh[nf]);
                }
        }
    }

    /* --- epilogue: bias add + coalesced float2 stores --- */
    #pragma unroll
    for (int mf = 0; mf < 2; mf++) {
        size_t r0 = (size_t)mtile * 128 + wm + mf * 16 + (lane >> 2);
        #pragma unroll
        for (int nf = 0; nf < 12; nf++) {
            int c = ntile * 192 + wn + nf * 8 + (lane & 3) * 2;
            float b0 = __ldg(bias + c), b1 = __ldg(bias + c + 1);
            *(float2*)(C + r0 * ldc + c) =
                make_float2(acc[mf][nf][0] + b0, acc[mf][nf][1] + b1);
            *(float2*)(C + (r0 + 8) * ldc + c) =
                make_float2(acc[mf][nf][2] + b0, acc[mf][nf][3] + b1);
        }
    }
}

/* ================= K2: per-window attention (scalar fp32) ================= */
/* smem floats: skT 9984 | sv 9504 | sp 2912 | spq 1792 = 24192 (96768 B) */
#define ATTN_SMEM (24192 * 4)

__global__ __launch_bounds__(256, 2)
void attn_win()
{
    extern __shared__ float smem[];
    float* skT = smem;              /* [h][d][n pad 52] */
    float* sv  = smem + 9984;       /* [h][n][32] + 96 zero pad */
    float* sp  = smem + 19488;      /* per-warp probs [8][7][52] */
    float* spq = smem + 22400;      /* per-warp q [8][7][32] */

    const int tid = threadIdx.x, b = blockIdx.x;
    const float* qkvw = g_qkv + (size_t)b * (NTOK * 576);

    for (int i = tid; i < NTOK * 384; i += 256) {
        int n = i / 384, c = i - n * 384;
        float val = qkvw[n * 576 + 192 + c];
        if (c < 192) { int h = c >> 5, d = c & 31; skT[(h * DH + d) * 52 + n] = val; }
        else { int c2 = c - 192; int h = c2 >> 5, d = c2 & 31; sv[(h * NTOK + n) * DH + d] = val; }
    }
    if (tid < 96) sv[HEADS * NTOK * DH + tid] = 0.0f;
    __syncthreads();

    const int wid = tid >> 5, lane = tid & 31;
    float* spw = sp + wid * 364;
    float* sq  = spq + wid * 224;

    for (int u = wid; u < 42; u += 8) {
        const int h  = u / 7;
        const int n0 = (u - h * 7) * 7;
        const float* kh = skT + h * DH * 52;
        const float* vh = sv  + h * NTOK * DH;

        #pragma unroll
        for (int i = 0; i < 7; i++)
            sq[i * 32 + lane] = qkvw[(n0 + i) * 576 + h * DH + lane] * QSCALE;
        __syncwarp();

        float a0[7], a1[7];
        #pragma unroll
        for (int i = 0; i < 7; i++) { a0[i] = 0.f; a1[i] = 0.f; }
        #pragma unroll 4
        for (int d = 0; d < DH; d++) {
            float k0 = kh[d * 52 + lane];
            float k1 = (lane < 17) ? kh[d * 52 + 32 + lane] : 0.f;
            #pragma unroll
            for (int i = 0; i < 7; i++) {
                float qv = sq[i * 32 + d];
                a0[i] = fmaf(qv, k0, a0[i]);
                a1[i] = fmaf(qv, k1, a1[i]);
            }
        }

        #pragma unroll
        for (int i = 0; i < 7; i++) {
            int n = n0 + i;
            float s0 = a0[i] + __ldg(&g_bias[(h * NTOK + n) * NTOK + lane]);
            float s1 = -1e30f;
            if (lane < 17) s1 = a1[i] + __ldg(&g_bias[(h * NTOK + n) * NTOK + 32 + lane]);
            float mx = fmaxf(s0, s1);
            #pragma unroll
            for (int off = 16; off > 0; off >>= 1)
                mx = fmaxf(mx, __shfl_xor_sync(0xffffffffu, mx, off));
            float e0 = __expf(s0 - mx);
            float e1 = (lane < 17) ? __expf(s1 - mx) : 0.f;
            float sm = e0 + e1;
            #pragma unroll
            for (int off = 16; off > 0; off >>= 1)
                sm += __shfl_xor_sync(0xffffffffu, sm, off);
            float inv = 1.f / sm;
            spw[i * 52 + lane] = e0 * inv;
            if (lane < 20) spw[i * 52 + 32 + lane] = (lane < 17) ? e1 * inv : 0.f;
        }
        __syncwarp();

        float o[7];
        #pragma unroll
        for (int i = 0; i < 7; i++) o[i] = 0.f;
        #pragma unroll 2
        for (int mq = 0; mq < 13; mq++) {
            int mb = mq * 4;
            float v0 = vh[(mb + 0) * DH + lane];
            float v1 = vh[(mb + 1) * DH + lane];
            float v2 = vh[(mb + 2) * DH + lane];
            float v3 = vh[(mb + 3) * DH + lane];
            #pragma unroll
            for (int i = 0; i < 7; i++) {
                float4 p = *(const float4*)&spw[i * 52 + mb];
                o[i] = fmaf(p.x, v0, o[i]);
                o[i] = fmaf(p.y, v1, o[i]);
                o[i] = fmaf(p.z, v2, o[i]);
                o[i] = fmaf(p.w, v3, o[i]);
            }
        }
        #pragma unroll
        for (int i = 0; i < 7; i++)
            g_attn[(size_t)(b * NTOK + n0 + i) * DIM + h * DH + lane] = o[i];
        __syncwarp();
    }
}

/* ================= host ================= */
extern "C" void kernel_launch(void* const* d_in, const int* in_sizes, int n_in,
                              void* d_out, int out_size)
{
    const float* x          = (const float*)d_in[0];
    const float* qkv_w      = (const float*)d_in[1];
    const float* qkv_b      = (const float*)d_in[2];
    const float* proj_w     = (const float*)d_in[3];
    const float* proj_b     = (const float*)d_in[4];
    const float* bias_table = (const float*)d_in[5];
    const int*   rel_idx    = (const int*)d_in[6];
    float*       out        = (float*)d_out;

    const int nB = in_sizes[0] / (NTOK * DIM);       /* 4096 */
    const int mt = (nB * NTOK) / 128;                /* 1568 */

    void *p_qkv, *p_attn, *p_wqh, *p_wql, *p_wph, *p_wpl;
    cudaGetSymbolAddress(&p_qkv,  g_qkv);
    cudaGetSymbolAddress(&p_attn, g_attn);
    cudaGetSymbolAddress(&p_wqh,  g_wqh);
    cudaGetSymbolAddress(&p_wql,  g_wql);
    cudaGetSymbolAddress(&p_wph,  g_wph);
    cudaGetSymbolAddress(&p_wpl,  g_wpl);

    cudaFuncSetAttribute(gemm_bf16x3, cudaFuncAttributeMaxDynamicSharedMemorySize, GEMM_SMEM);
    cudaFuncSetAttribute(attn_win,    cudaFuncAttributeMaxDynamicSharedMemorySize, ATTN_SMEM);

    prep_kernel<<<432, 256>>>(qkv_w, proj_w, bias_table, rel_idx);

    gemm_bf16x3<<<dim3(mt, 3), 256, GEMM_SMEM>>>(
        x, (const __nv_bfloat16*)p_wqh, (const __nv_bfloat16*)p_wql,
        qkv_b, (float*)p_qkv, 576);

    attn_win<<<nB, 256, ATTN_SMEM>>>();

    gemm_bf16x3<<<dim3(mt, 1), 256, GEMM_SMEM>>>(
        (const float*)p_attn, (const __nv_bfloat16*)p_wph, (const __nv_bfloat16*)p_wpl,
        proj_b, out, 192);
}

// round 5
// speedup vs baseline: 4.0466x; 1.4153x over previous
#include <cuda_runtime.h>
#include <cuda_bf16.h>
#include <cstdint>
#include <math.h>

#define NTOK   49
#define HEADS  6
#define DIM    192
#define DH     32
#define QSCALE 0.1767766952966369f

/* ================= device scratch (static: allocation-free) ================= */
__device__ float          g_qkv [200704u * 576u];   /* 462 MB qkv intermediate  */
__device__ float          g_attn[200704u * 192u];   /* 154 MB attention output  */
__device__ __nv_bfloat16  g_wqh[576 * 192], g_wql[576 * 192];
__device__ __nv_bfloat16  g_wph[192 * 192], g_wpl[192 * 192];
__device__ float          g_bias[HEADS * NTOK * NTOK];

__device__ __forceinline__ uint32_t pack_bf2(float a, float b) {
    __nv_bfloat16 ha = __float2bfloat16(a), hb = __float2bfloat16(b);
    return (uint32_t)__bfloat16_as_ushort(ha) | ((uint32_t)__bfloat16_as_ushort(hb) << 16);
}

/* ================= prep: split weights to bf16 hi/lo, materialize bias ================= */
__global__ void prep_kernel(const float* __restrict__ qkv_w, const float* __restrict__ proj_w,
                            const float* __restrict__ bias_table, const int* __restrict__ rel_idx)
{
    int i = blockIdx.x * 256 + threadIdx.x;
    if (i < 576 * 192) {
        float w = qkv_w[i];
        __nv_bfloat16 h = __float2bfloat16(w);
        g_wqh[i] = h;
        g_wql[i] = __float2bfloat16(w - __bfloat162float(h));
    }
    if (i < 192 * 192) {
        float w = proj_w[i];
        __nv_bfloat16 h = __float2bfloat16(w);
        g_wph[i] = h;
        g_wpl[i] = __float2bfloat16(w - __bfloat162float(h));
    }
    if (i < HEADS * NTOK * NTOK) {
        int m = i % NTOK, t = i / NTOK;
        int n = t % NTOK, h = t / NTOK;
        g_bias[i] = bias_table[rel_idx[n * NTOK + m] * HEADS + h];
    }
}

/* ================= mma.sync bf16 m16n8k16 ================= */
__device__ __forceinline__ void mma16816(float* c, const uint32_t* a, const uint32_t* b) {
    asm volatile(
        "mma.sync.aligned.m16n8k16.row.col.f32.bf16.bf16.f32 "
        "{%0,%1,%2,%3}, {%4,%5,%6,%7}, {%8,%9}, {%0,%1,%2,%3};"
        : "+f"(c[0]), "+f"(c[1]), "+f"(c[2]), "+f"(c[3])
        : "r"(a[0]), "r"(a[1]), "r"(a[2]), "r"(a[3]), "r"(b[0]), "r"(b[1]));
}

/* ================ GEMM (unchanged from passing R4 kernel) ================ */
#define SM_AH 0
#define SM_AL 18432
#define SM_BH 36864
#define SM_BL 64512
#define GEMM_SMEM 92160

__global__ __launch_bounds__(256, 1)
void gemm_bf16x3(const float* __restrict__ A,
                 const __nv_bfloat16* __restrict__ Bhi,
                 const __nv_bfloat16* __restrict__ Blo,
                 const float* __restrict__ bias,
                 float* __restrict__ C, int ldc)
{
    extern __shared__ char smc[];
    const int tid = threadIdx.x, wid = tid >> 5, lane = tid & 31;
    const int mtile = blockIdx.x, ntile = blockIdx.y;

    const int wm = (wid & 3) * 32;
    const int wn = (wid >> 2) * 96;

    const float* Abase = A + (size_t)mtile * 128 * 192;
    const __nv_bfloat16* Bhb = Bhi + (size_t)ntile * 192 * 192;
    const __nv_bfloat16* Blb = Blo + (size_t)ntile * 192 * 192;

    float acc[2][12][4];
    #pragma unroll
    for (int mf = 0; mf < 2; mf++)
        #pragma unroll
        for (int nf = 0; nf < 12; nf++)
            #pragma unroll
            for (int j = 0; j < 4; j++) acc[mf][nf][j] = 0.f;

    for (int kc = 0; kc < 3; kc++) {
        if (kc) __syncthreads();

        #pragma unroll
        for (int it = 0; it < 8; it++) {
            int g   = tid + it * 256;
            int row = g >> 4, c4 = (g & 15) << 2;
            float4 f = *(const float4*)(Abase + row * 192 + kc * 64 + c4);
            uint32_t h0 = pack_bf2(f.x, f.y), h1 = pack_bf2(f.z, f.w);
            float rx = f.x - __bfloat162float(__ushort_as_bfloat16((unsigned short)h0));
            float ry = f.y - __bfloat162float(__ushort_as_bfloat16((unsigned short)(h0 >> 16)));
            float rz = f.z - __bfloat162float(__ushort_as_bfloat16((unsigned short)h1));
            float rw = f.w - __bfloat162float(__ushort_as_bfloat16((unsigned short)(h1 >> 16)));
            uint32_t l0 = pack_bf2(rx, ry), l1 = pack_bf2(rz, rw);
            *(uint2*)(smc + SM_AH + row * 144 + c4 * 2) = make_uint2(h0, h1);
            *(uint2*)(smc + SM_AL + row * 144 + c4 * 2) = make_uint2(l0, l1);
        }
        #pragma unroll
        for (int it = 0; it < 6; it++) {
            int g   = tid + it * 256;
            int row = g >> 3, c8 = (g & 7) << 3;
            uint4 u = *(const uint4*)(Bhb + row * 192 + kc * 64 + c8);
            uint4 w = *(const uint4*)(Blb + row * 192 + kc * 64 + c8);
            *(uint4*)(smc + SM_BH + row * 144 + c8 * 2) = u;
            *(uint4*)(smc + SM_BL + row * 144 + c8 * 2) = w;
        }
        __syncthreads();

        #pragma unroll
        for (int ks = 0; ks < 4; ks++) {
            const int kk = ks * 16 + (lane & 3) * 2;

            uint32_t ah[2][4], al[2][4];
            #pragma unroll
            for (int mf = 0; mf < 2; mf++)
                #pragma unroll
                for (int rgi = 0; rgi < 4; rgi++) {
                    int rr = wm + mf * 16 + (lane >> 2) + (rgi & 1) * 8;
                    int kx = kk + (rgi >> 1) * 8;
                    ah[mf][rgi] = *(const uint32_t*)(smc + SM_AH + rr * 144 + kx * 2);
                    al[mf][rgi] = *(const uint32_t*)(smc + SM_AL + rr * 144 + kx * 2);
                }

            uint32_t bh[12][2], bl[12][2];
            #pragma unroll
            for (int nf = 0; nf < 12; nf++) {
                int n = wn + nf * 8 + (lane >> 2);
                bh[nf][0] = *(const uint32_t*)(smc + SM_BH + n * 144 + kk * 2);
                bh[nf][1] = *(const uint32_t*)(smc + SM_BH + n * 144 + (kk + 8) * 2);
                bl[nf][0] = *(const uint32_t*)(smc + SM_BL + n * 144 + kk * 2);
                bl[nf][1] = *(const uint32_t*)(smc + SM_BL + n * 144 + (kk + 8) * 2);
            }

            #pragma unroll
            for (int mf = 0; mf < 2; mf++)
                #pragma unroll
                for (int nf = 0; nf < 12; nf++) {
                    mma16816(acc[mf][nf], ah[mf], bh[nf]);
                    mma16816(acc[mf][nf], ah[mf], bl[nf]);
                    mma16816(acc[mf][nf], al[mf], bh[nf]);
                }
        }
    }

    #pragma unroll
    for (int mf = 0; mf < 2; mf++) {
        size_t r0 = (size_t)mtile * 128 + wm + mf * 16 + (lane >> 2);
        #pragma unroll
        for (int nf = 0; nf < 12; nf++) {
            int c = ntile * 192 + wn + nf * 8 + (lane & 3) * 2;
            float b0 = __ldg(bias + c), b1 = __ldg(bias + c + 1);
            *(float2*)(C + r0 * ldc + c) =
                make_float2(acc[mf][nf][0] + b0, acc[mf][nf][1] + b1);
            *(float2*)(C + (r0 + 8) * ldc + c) =
                make_float2(acc[mf][nf][2] + b0, acc[mf][nf][3] + b1);
        }
    }
}

/* ================= K2: tensorized per-window attention =================
   1 CTA (128 thr) per window. Per head: convert q*scale/k/v -> hi/lo bf16
   smem tiles; warp w owns rows [w*16, w*16+16): S = QK^T (3-term HMMA),
   register softmax, P hi/lo re-split, O = P V (3-term HMMA), store. */

__global__ __launch_bounds__(128, 3)
void attn_win()
{
    /* padded tiles: Q [64][36], K [56][36], VT [32][66] (bf16 hi/lo) */
    __shared__ __nv_bfloat16 sQh[64 * 36], sQl[64 * 36];
    __shared__ __nv_bfloat16 sKh[56 * 36], sKl[56 * 36];
    __shared__ __nv_bfloat16 sVh[32 * 66], sVl[32 * 66];

    const int tid  = threadIdx.x;
    const int wid  = tid >> 5, lane = tid & 31;
    const int b    = blockIdx.x;
    const int l4   = lane >> 2, lm = lane & 3;

    /* zero all tiles once; per-head writes cover only real regions so pads stay 0 */
    for (int i = tid; i < 64 * 36; i += 128) { sQh[i] = __nv_bfloat16(0.f); sQl[i] = __nv_bfloat16(0.f); }
    for (int i = tid; i < 56 * 36; i += 128) { sKh[i] = __nv_bfloat16(0.f); sKl[i] = __nv_bfloat16(0.f); }
    for (int i = tid; i < 32 * 66; i += 128) { sVh[i] = __nv_bfloat16(0.f); sVl[i] = __nv_bfloat16(0.f); }

    const float* qkvw = g_qkv + (size_t)b * (NTOK * 576);
    const int r0 = wid * 16 + l4;            /* this thread's row (and r0+8) */

    for (int h = 0; h < HEADS; h++) {
        __syncthreads();
        /* ---- convert phase: 49x32 q,k,v -> hi/lo tiles ---- */
        for (int idx = tid; idx < NTOK * 32; idx += 128) {
            int r = idx >> 5, c = idx & 31;
            const float* rowp = qkvw + r * 576 + h * 32 + c;
            float qv = rowp[0] * QSCALE;
            float kv = rowp[192];
            float vv = rowp[384];
            __nv_bfloat16 qh = __float2bfloat16(qv);
            __nv_bfloat16 kh = __float2bfloat16(kv);
            __nv_bfloat16 vh = __float2bfloat16(vv);
            sQh[r * 36 + c] = qh; sQl[r * 36 + c] = __float2bfloat16(qv - __bfloat162float(qh));
            sKh[r * 36 + c] = kh; sKl[r * 36 + c] = __float2bfloat16(kv - __bfloat162float(kh));
            sVh[c * 66 + r] = vh; sVl[c * 66 + r] = __float2bfloat16(vv - __bfloat162float(vh));
        }
        __syncthreads();

        /* ---- Q a-frags (M=16 rows r0/r0+8, K=32) ---- */
        uint32_t qh[2][4], ql[2][4];
        #pragma unroll
        for (int kf = 0; kf < 2; kf++)
            #pragma unroll
            for (int j = 0; j < 4; j++) {
                int rr = r0 + (j & 1) * 8;
                int kx = kf * 16 + lm * 2 + (j >> 1) * 8;
                qh[kf][j] = *(const uint32_t*)&sQh[rr * 36 + kx];
                ql[kf][j] = *(const uint32_t*)&sQl[rr * 36 + kx];
            }

        /* ---- S = Q K^T, 3-term ---- */
        float acc[7][4];
        #pragma unroll
        for (int nf = 0; nf < 7; nf++)
            #pragma unroll
            for (int j = 0; j < 4; j++) acc[nf][j] = 0.f;

        #pragma unroll
        for (int nf = 0; nf < 7; nf++) {
            int n = nf * 8 + l4;
            #pragma unroll
            for (int kf = 0; kf < 2; kf++) {
                uint32_t bh[2], bl[2];
                bh[0] = *(const uint32_t*)&sKh[n * 36 + kf * 16 + lm * 2];
                bh[1] = *(const uint32_t*)&sKh[n * 36 + kf * 16 + lm * 2 + 8];
                bl[0] = *(const uint32_t*)&sKl[n * 36 + kf * 16 + lm * 2];
                bl[1] = *(const uint32_t*)&sKl[n * 36 + kf * 16 + lm * 2 + 8];
                mma16816(acc[nf], qh[kf], bh);
                mma16816(acc[nf], ql[kf], bh);
                mma16816(acc[nf], qh[kf], bl);
            }
        }

        /* ---- softmax (rows r0, r0+8 fully within the 4-lane quad) ---- */
        const int ra = r0, rb = r0 + 8;
        const float* biasA = g_bias + (h * NTOK + ra) * NTOK;
        const float* biasB = g_bias + (h * NTOK + rb) * NTOK;
        float ma = -1e30f, mb = -1e30f;
        #pragma unroll
        for (int nf = 0; nf < 7; nf++) {
            int c0 = nf * 8 + lm * 2, c1 = c0 + 1;
            float ba0 = (ra < NTOK && c0 < NTOK) ? __ldg(biasA + c0) : 0.f;
            float ba1 = (ra < NTOK && c1 < NTOK) ? __ldg(biasA + c1) : 0.f;
            float bb0 = (rb < NTOK && c0 < NTOK) ? __ldg(biasB + c0) : 0.f;
            float bb1 = (rb < NTOK && c1 < NTOK) ? __ldg(biasB + c1) : 0.f;
            acc[nf][0] = (c0 < NTOK) ? acc[nf][0] + ba0 : -1e30f;
            acc[nf][1] = (c1 < NTOK) ? acc[nf][1] + ba1 : -1e30f;
            acc[nf][2] = (c0 < NTOK) ? acc[nf][2] + bb0 : -1e30f;
            acc[nf][3] = (c1 < NTOK) ? acc[nf][3] + bb1 : -1e30f;
            ma = fmaxf(ma, fmaxf(acc[nf][0], acc[nf][1]));
            mb = fmaxf(mb, fmaxf(acc[nf][2], acc[nf][3]));
        }
        ma = fmaxf(ma, __shfl_xor_sync(0xffffffffu, ma, 1));
        ma = fmaxf(ma, __shfl_xor_sync(0xffffffffu, ma, 2));
        mb = fmaxf(mb, __shfl_xor_sync(0xffffffffu, mb, 1));
        mb = fmaxf(mb, __shfl_xor_sync(0xffffffffu, mb, 2));

        float sa = 0.f, sb = 0.f;
        #pragma unroll
        for (int nf = 0; nf < 7; nf++) {
            acc[nf][0] = __expf(acc[nf][0] - ma);
            acc[nf][1] = __expf(acc[nf][1] - ma);
            acc[nf][2] = __expf(acc[nf][2] - mb);
            acc[nf][3] = __expf(acc[nf][3] - mb);
            sa += acc[nf][0] + acc[nf][1];
            sb += acc[nf][2] + acc[nf][3];
        }
        sa += __shfl_xor_sync(0xffffffffu, sa, 1);
        sa += __shfl_xor_sync(0xffffffffu, sa, 2);
        sb += __shfl_xor_sync(0xffffffffu, sb, 1);
        sb += __shfl_xor_sync(0xffffffffu, sb, 2);
        float inva = 1.f / sa, invb = 1.f / sb;
        #pragma unroll
        for (int nf = 0; nf < 7; nf++) {
            acc[nf][0] *= inva; acc[nf][1] *= inva;
            acc[nf][2] *= invb; acc[nf][3] *= invb;
        }

        /* ---- P hi/lo a-frags (K=64; kf=3 upper half zero) ---- */
        uint32_t pah[4][4], pal[4][4];
        #pragma unroll
        for (int kf = 0; kf < 4; kf++) {
            #pragma unroll
            for (int half = 0; half < 2; half++) {   /* nf = 2kf+half */
                int nf = 2 * kf + half;
                if (nf < 7) {
                    float p0 = acc[nf][0], p1 = acc[nf][1];
                    float p2 = acc[nf][2], p3 = acc[nf][3];
                    uint32_t h01 = pack_bf2(p0, p1), h23 = pack_bf2(p2, p3);
                    float r0f = p0 - __bfloat162float(__ushort_as_bfloat16((unsigned short)h01));
                    float r1f = p1 - __bfloat162float(__ushort_as_bfloat16((unsigned short)(h01 >> 16)));
                    float r2f = p2 - __bfloat162float(__ushort_as_bfloat16((unsigned short)h23));
                    float r3f = p3 - __bfloat162float(__ushort_as_bfloat16((unsigned short)(h23 >> 16)));
                    pah[kf][half * 2]     = h01;
                    pah[kf][half * 2 + 1] = h23;
                    pal[kf][half * 2]     = pack_bf2(r0f, r1f);
                    pal[kf][half * 2 + 1] = pack_bf2(r2f, r3f);
                } else {
                    pah[kf][half * 2] = 0u; pah[kf][half * 2 + 1] = 0u;
                    pal[kf][half * 2] = 0u; pal[kf][half * 2 + 1] = 0u;
                }
            }
        }

        /* ---- O = P V, 3-term ---- */
        float oacc[4][4];
        #pragma unroll
        for (int nf = 0; nf < 4; nf++)
            #pragma unroll
            for (int j = 0; j < 4; j++) oacc[nf][j] = 0.f;

        #pragma unroll
        for (int nf = 0; nf < 4; nf++) {
            int dh = nf * 8 + l4;
            #pragma unroll
            for (int kf = 0; kf < 4; kf++) {
                uint32_t bh[2], bl[2];
                bh[0] = *(const uint32_t*)&sVh[dh * 66 + kf * 16 + lm * 2];
                bh[1] = *(const uint32_t*)&sVh[dh * 66 + kf * 16 + lm * 2 + 8];
                bl[0] = *(const uint32_t*)&sVl[dh * 66 + kf * 16 + lm * 2];
                bl[1] = *(const uint32_t*)&sVl[dh * 66 + kf * 16 + lm * 2 + 8];
                mma16816(oacc[nf], pah[kf], bh);
                mma16816(oacc[nf], pal[kf], bh);
                mma16816(oacc[nf], pah[kf], bl);
            }
        }

        /* ---- store O rows < 49 ---- */
        if (ra < NTOK) {
            float* orow = g_attn + ((size_t)b * NTOK + ra) * DIM + h * DH;
            #pragma unroll
            for (int nf = 0; nf < 4; nf++)
                *(float2*)(orow + nf * 8 + lm * 2) = make_float2(oacc[nf][0], oacc[nf][1]);
        }
        if (rb < NTOK) {
            float* orow = g_attn + ((size_t)b * NTOK + rb) * DIM + h * DH;
            #pragma unroll
            for (int nf = 0; nf < 4; nf++)
                *(float2*)(orow + nf * 8 + lm * 2) = make_float2(oacc[nf][2], oacc[nf][3]);
        }
    }
}

/* ================= host ================= */
extern "C" void kernel_launch(void* const* d_in, const int* in_sizes, int n_in,
                              void* d_out, int out_size)
{
    const float* x          = (const float*)d_in[0];
    const float* qkv_w      = (const float*)d_in[1];
    const float* qkv_b      = (const float*)d_in[2];
    const float* proj_w     = (const float*)d_in[3];
    const float* proj_b     = (const float*)d_in[4];
    const float* bias_table = (const float*)d_in[5];
    const int*   rel_idx    = (const int*)d_in[6];
    float*       out        = (float*)d_out;

    const int nB = in_sizes[0] / (NTOK * DIM);       /* 4096 */
    const int mt = (nB * NTOK) / 128;                /* 1568 */

    void *p_qkv, *p_attn, *p_wqh, *p_wql, *p_wph, *p_wpl;
    cudaGetSymbolAddress(&p_qkv,  g_qkv);
    cudaGetSymbolAddress(&p_attn, g_attn);
    cudaGetSymbolAddress(&p_wqh,  g_wqh);
    cudaGetSymbolAddress(&p_wql,  g_wql);
    cudaGetSymbolAddress(&p_wph,  g_wph);
    cudaGetSymbolAddress(&p_wpl,  g_wpl);

    cudaFuncSetAttribute(gemm_bf16x3, cudaFuncAttributeMaxDynamicSharedMemorySize, GEMM_SMEM);

    prep_kernel<<<432, 256>>>(qkv_w, proj_w, bias_table, rel_idx);

    gemm_bf16x3<<<dim3(mt, 3), 256, GEMM_SMEM>>>(
        x, (const __nv_bfloat16*)p_wqh, (const __nv_bfloat16*)p_wql,
        qkv_b, (float*)p_qkv, 576);

    attn_win<<<nB, 128>>>();

    gemm_bf16x3<<<dim3(mt, 1), 256, GEMM_SMEM>>>(
        (const float*)p_attn, (const __nv_bfloat16*)p_wph, (const __nv_bfloat16*)p_wpl,
        proj_b, out, 192);
}

// round 6
// speedup vs baseline: 4.1471x; 1.0248x over previous
#include <cuda_runtime.h>
#include <cuda_bf16.h>
#include <cstdint>
#include <math.h>

#define NTOK   49
#define HEADS  6
#define DIM    192
#define DH     32
#define QSCALE 0.1767766952966369f

/* ================= device scratch (static: allocation-free) ================= */
__device__ float          g_qkv [200704u * 576u];   /* 462 MB qkv intermediate  */
__device__ float          g_attn[200704u * 192u];   /* 154 MB attention output  */
__device__ __nv_bfloat16  g_wqh[576 * 192], g_wql[576 * 192];
__device__ __nv_bfloat16  g_wph[192 * 192], g_wpl[192 * 192];
__device__ float          g_bias[HEADS * NTOK * NTOK];

__device__ __forceinline__ uint32_t pack_bf2(float a, float b) {
    __nv_bfloat16 ha = __float2bfloat16(a), hb = __float2bfloat16(b);
    return (uint32_t)__bfloat16_as_ushort(ha) | ((uint32_t)__bfloat16_as_ushort(hb) << 16);
}

/* ================= prep: split weights to bf16 hi/lo, materialize bias ================= */
__global__ void prep_kernel(const float* __restrict__ qkv_w, const float* __restrict__ proj_w,
                            const float* __restrict__ bias_table, const int* __restrict__ rel_idx)
{
    int i = blockIdx.x * 256 + threadIdx.x;
    if (i < 576 * 192) {
        float w = qkv_w[i];
        __nv_bfloat16 h = __float2bfloat16(w);
        g_wqh[i] = h;
        g_wql[i] = __float2bfloat16(w - __bfloat162float(h));
    }
    if (i < 192 * 192) {
        float w = proj_w[i];
        __nv_bfloat16 h = __float2bfloat16(w);
        g_wph[i] = h;
        g_wpl[i] = __float2bfloat16(w - __bfloat162float(h));
    }
    if (i < HEADS * NTOK * NTOK) {
        int m = i % NTOK, t = i / NTOK;
        int n = t % NTOK, h = t / NTOK;
        g_bias[i] = bias_table[rel_idx[n * NTOK + m] * HEADS + h];
    }
}

/* ================= mma.sync bf16 m16n8k16 ================= */
__device__ __forceinline__ void mma16816(float* c, const uint32_t* a, const uint32_t* b) {
    asm volatile(
        "mma.sync.aligned.m16n8k16.row.col.f32.bf16.bf16.f32 "
        "{%0,%1,%2,%3}, {%4,%5,%6,%7}, {%8,%9}, {%0,%1,%2,%3};"
        : "+f"(c[0]), "+f"(c[1]), "+f"(c[2]), "+f"(c[3])
        : "r"(a[0]), "r"(a[1]), "r"(a[2]), "r"(a[3]), "r"(b[0]), "r"(b[1]));
}

__device__ __forceinline__ void cp16(uint32_t dst, const void* src) {
    asm volatile("cp.async.cg.shared.global [%0], [%1], 16;" :: "r"(dst), "l"(src));
}

/* ================ GEMM v2: A smem-resident, cp.async double-buffered B ================
   C[128, N] strip per CTA. A (128x192 fp32) converted ONCE to hi/lo bf16 smem
   (rows padded to 200 bf16 = 400 B -> conflict-free a-frag loads). B chunks
   (192x64 bf16 hi/lo, rows padded to 72) streamed via cp.async, 2-deep.       */
#define APAD   200
#define A_H    0
#define A_L    (128 * APAD * 2)                /* 51200  */
#define B_BASE (2 * 128 * APAD * 2)            /* 102400 */
#define B_STEP 55296                            /* per buffer: hi 27648 + lo 27648 */
#define B_LO   27648
#define GEMM_SMEM (B_BASE + 2 * B_STEP)        /* 212992 */

__global__ __launch_bounds__(256, 1)
void gemm_bf16x3(const float* __restrict__ A,
                 const __nv_bfloat16* __restrict__ Bhi,
                 const __nv_bfloat16* __restrict__ Blo,
                 const float* __restrict__ bias,
                 float* __restrict__ C, int ldc, int NT)
{
    extern __shared__ char smc[];
    uint32_t sb;
    asm("{ .reg .u64 t; cvta.to.shared.u64 t, %1; cvt.u32.u64 %0, t; }" : "=r"(sb) : "l"(smc));

    const int tid = threadIdx.x, wid = tid >> 5, lane = tid & 31;
    const int mtile = blockIdx.x;
    const int wm = (wid & 3) * 32;
    const int wn = (wid >> 2) * 96;
    const int L  = 3 * NT;

    /* ---- prefetch helper (chunk idx -> buffer idx&1) ---- */
    auto prefetch = [&](int idx) {
        int nt = idx / 3, kc = idx - nt * 3;
        const __nv_bfloat16* bh = Bhi + (size_t)nt * 192 * 192 + kc * 64;
        const __nv_bfloat16* bl = Blo + (size_t)nt * 192 * 192 + kc * 64;
        uint32_t dst = sb + B_BASE + (idx & 1) * B_STEP;
        #pragma unroll
        for (int it = 0; it < 6; it++) {
            int g = tid + it * 256;          /* 1536 groups */
            int row = g >> 3, c8 = g & 7;
            cp16(dst + row * 144 + c8 * 16, bh + row * 192 + c8 * 8);
            cp16(dst + B_LO + row * 144 + c8 * 16, bl + row * 192 + c8 * 8);
        }
        asm volatile("cp.async.commit_group;" ::: "memory");
    };

    prefetch(0);
    if (L > 1) prefetch(1);

    /* ---- A: load 128x192 fp32, split hi/lo into smem (once) ---- */
    {
        const float* Abase = A + (size_t)mtile * 128 * 192;
        #pragma unroll
        for (int it = 0; it < 24; it++) {
            int g = tid + it * 256;           /* 6144 float4 groups */
            int row = g / 48, c4 = (g % 48) * 4;
            float4 f = *(const float4*)(Abase + row * 192 + c4);
            uint32_t h0 = pack_bf2(f.x, f.y), h1 = pack_bf2(f.z, f.w);
            float rx = f.x - __bfloat162float(__ushort_as_bfloat16((unsigned short)h0));
            float ry = f.y - __bfloat162float(__ushort_as_bfloat16((unsigned short)(h0 >> 16)));
            float rz = f.z - __bfloat162float(__ushort_as_bfloat16((unsigned short)h1));
            float rw = f.w - __bfloat162float(__ushort_as_bfloat16((unsigned short)(h1 >> 16)));
            *(uint2*)(smc + A_H + row * 400 + c4 * 2) = make_uint2(h0, h1);
            *(uint2*)(smc + A_L + row * 400 + c4 * 2) =
                make_uint2(pack_bf2(rx, ry), pack_bf2(rz, rw));
        }
    }
    __syncthreads();

    float acc[2][12][4];

    for (int nt = 0; nt < NT; nt++) {
        #pragma unroll
        for (int mf = 0; mf < 2; mf++)
            #pragma unroll
            for (int nf = 0; nf < 12; nf++)
                #pragma unroll
                for (int j = 0; j < 4; j++) acc[mf][nf][j] = 0.f;

        for (int kc = 0; kc < 3; kc++) {
            const int idx = nt * 3 + kc;
            if (idx < L - 1) asm volatile("cp.async.wait_group 1;" ::: "memory");
            else             asm volatile("cp.async.wait_group 0;" ::: "memory");
            __syncthreads();

            const char* bb = smc + B_BASE + (idx & 1) * B_STEP;

            #pragma unroll
            for (int ks = 0; ks < 4; ks++) {
                const int kk  = ks * 16 + (lane & 3) * 2;       /* bf16 idx in chunk */
                const int kxg = kc * 64 + kk;                    /* bf16 idx in A row */

                uint32_t ah[2][4], al[2][4];
                #pragma unroll
                for (int mf = 0; mf < 2; mf++)
                    #pragma unroll
                    for (int j = 0; j < 4; j++) {
                        int rr = wm + mf * 16 + (lane >> 2) + (j & 1) * 8;
                        int kx = kxg + (j >> 1) * 8;
                        ah[mf][j] = *(const uint32_t*)(smc + A_H + rr * 400 + kx * 2);
                        al[mf][j] = *(const uint32_t*)(smc + A_L + rr * 400 + kx * 2);
                    }

                uint32_t bh[12][2], bl[12][2];
                #pragma unroll
                for (int nf = 0; nf < 12; nf++) {
                    int n = wn + nf * 8 + (lane >> 2);
                    bh[nf][0] = *(const uint32_t*)(bb + n * 144 + kk * 2);
                    bh[nf][1] = *(const uint32_t*)(bb + n * 144 + (kk + 8) * 2);
                    bl[nf][0] = *(const uint32_t*)(bb + B_LO + n * 144 + kk * 2);
                    bl[nf][1] = *(const uint32_t*)(bb + B_LO + n * 144 + (kk + 8) * 2);
                }

                #pragma unroll
                for (int mf = 0; mf < 2; mf++)
                    #pragma unroll
                    for (int nf = 0; nf < 12; nf++) {
                        mma16816(acc[mf][nf], ah[mf], bh[nf]);
                        mma16816(acc[mf][nf], ah[mf], bl[nf]);
                        mma16816(acc[mf][nf], al[mf], bh[nf]);
                    }
            }
            __syncthreads();
            if (idx + 2 < L) prefetch(idx + 2);
        }

        /* ---- epilogue for this ntile (overlaps next chunk's cp.async) ---- */
        #pragma unroll
        for (int mf = 0; mf < 2; mf++) {
            size_t r0 = (size_t)mtile * 128 + wm + mf * 16 + (lane >> 2);
            #pragma unroll
            for (int nf = 0; nf < 12; nf++) {
                int c = nt * 192 + wn + nf * 8 + (lane & 3) * 2;
                float b0 = __ldg(bias + c), b1 = __ldg(bias + c + 1);
                *(float2*)(C + r0 * ldc + c) =
                    make_float2(acc[mf][nf][0] + b0, acc[mf][nf][1] + b1);
                *(float2*)(C + (r0 + 8) * ldc + c) =
                    make_float2(acc[mf][nf][2] + b0, acc[mf][nf][3] + b1);
            }
        }
    }
}

/* ================= K2: tensorized per-window attention (unchanged, passing) ========== */
__global__ __launch_bounds__(128, 3)
void attn_win()
{
    __shared__ __nv_bfloat16 sQh[64 * 36], sQl[64 * 36];
    __shared__ __nv_bfloat16 sKh[56 * 36], sKl[56 * 36];
    __shared__ __nv_bfloat16 sVh[32 * 66], sVl[32 * 66];

    const int tid  = threadIdx.x;
    const int wid  = tid >> 5, lane = tid & 31;
    const int b    = blockIdx.x;
    const int l4   = lane >> 2, lm = lane & 3;

    for (int i = tid; i < 64 * 36; i += 128) { sQh[i] = __nv_bfloat16(0.f); sQl[i] = __nv_bfloat16(0.f); }
    for (int i = tid; i < 56 * 36; i += 128) { sKh[i] = __nv_bfloat16(0.f); sKl[i] = __nv_bfloat16(0.f); }
    for (int i = tid; i < 32 * 66; i += 128) { sVh[i] = __nv_bfloat16(0.f); sVl[i] = __nv_bfloat16(0.f); }

    const float* qkvw = g_qkv + (size_t)b * (NTOK * 576);
    const int r0 = wid * 16 + l4;

    for (int h = 0; h < HEADS; h++) {
        __syncthreads();
        for (int idx = tid; idx < NTOK * 32; idx += 128) {
            int r = idx >> 5, c = idx & 31;
            const float* rowp = qkvw + r * 576 + h * 32 + c;
            float qv = rowp[0] * QSCALE;
            float kv = rowp[192];
            float vv = rowp[384];
            __nv_bfloat16 qh = __float2bfloat16(qv);
            __nv_bfloat16 kh = __float2bfloat16(kv);
            __nv_bfloat16 vh = __float2bfloat16(vv);
            sQh[r * 36 + c] = qh; sQl[r * 36 + c] = __float2bfloat16(qv - __bfloat162float(qh));
            sKh[r * 36 + c] = kh; sKl[r * 36 + c] = __float2bfloat16(kv - __bfloat162float(kh));
            sVh[c * 66 + r] = vh; sVl[c * 66 + r] = __float2bfloat16(vv - __bfloat162float(vh));
        }
        __syncthreads();

        uint32_t qh[2][4], ql[2][4];
        #pragma unroll
        for (int kf = 0; kf < 2; kf++)
            #pragma unroll
            for (int j = 0; j < 4; j++) {
                int rr = r0 + (j & 1) * 8;
                int kx = kf * 16 + lm * 2 + (j >> 1) * 8;
                qh[kf][j] = *(const uint32_t*)&sQh[rr * 36 + kx];
                ql[kf][j] = *(const uint32_t*)&sQl[rr * 36 + kx];
            }

        float acc[7][4];
        #pragma unroll
        for (int nf = 0; nf < 7; nf++)
            #pragma unroll
            for (int j = 0; j < 4; j++) acc[nf][j] = 0.f;

        #pragma unroll
        for (int nf = 0; nf < 7; nf++) {
            int n = nf * 8 + l4;
            #pragma unroll
            for (int kf = 0; kf < 2; kf++) {
                uint32_t bh[2], bl[2];
                bh[0] = *(const uint32_t*)&sKh[n * 36 + kf * 16 + lm * 2];
                bh[1] = *(const uint32_t*)&sKh[n * 36 + kf * 16 + lm * 2 + 8];
                bl[0] = *(const uint32_t*)&sKl[n * 36 + kf * 16 + lm * 2];
                bl[1] = *(const uint32_t*)&sKl[n * 36 + kf * 16 + lm * 2 + 8];
                mma16816(acc[nf], qh[kf], bh);
                mma16816(acc[nf], ql[kf], bh);
                mma16816(acc[nf], qh[kf], bl);
            }
        }

        const int ra = r0, rb = r0 + 8;
        const float* biasA = g_bias + (h * NTOK + ra) * NTOK;
        const float* biasB = g_bias + (h * NTOK + rb) * NTOK;
        float ma = -1e30f, mb = -1e30f;
        #pragma unroll
        for (int nf = 0; nf < 7; nf++) {
            int c0 = nf * 8 + lm * 2, c1 = c0 + 1;
            float ba0 = (ra < NTOK && c0 < NTOK) ? __ldg(biasA + c0) : 0.f;
            float ba1 = (ra < NTOK && c1 < NTOK) ? __ldg(biasA + c1) : 0.f;
            float bb0 = (rb < NTOK && c0 < NTOK) ? __ldg(biasB + c0) : 0.f;
            float bb1 = (rb < NTOK && c1 < NTOK) ? __ldg(biasB + c1) : 0.f;
            acc[nf][0] = (c0 < NTOK) ? acc[nf][0] + ba0 : -1e30f;
            acc[nf][1] = (c1 < NTOK) ? acc[nf][1] + ba1 : -1e30f;
            acc[nf][2] = (c0 < NTOK) ? acc[nf][2] + bb0 : -1e30f;
            acc[nf][3] = (c1 < NTOK) ? acc[nf][3] + bb1 : -1e30f;
            ma = fmaxf(ma, fmaxf(acc[nf][0], acc[nf][1]));
            mb = fmaxf(mb, fmaxf(acc[nf][2], acc[nf][3]));
        }
        ma = fmaxf(ma, __shfl_xor_sync(0xffffffffu, ma, 1));
        ma = fmaxf(ma, __shfl_xor_sync(0xffffffffu, ma, 2));
        mb = fmaxf(mb, __shfl_xor_sync(0xffffffffu, mb, 1));
        mb = fmaxf(mb, __shfl_xor_sync(0xffffffffu, mb, 2));

        float sa = 0.f, sb2 = 0.f;
        #pragma unroll
        for (int nf = 0; nf < 7; nf++) {
            acc[nf][0] = __expf(acc[nf][0] - ma);
            acc[nf][1] = __expf(acc[nf][1] - ma);
            acc[nf][2] = __expf(acc[nf][2] - mb);
            acc[nf][3] = __expf(acc[nf][3] - mb);
            sa  += acc[nf][0] + acc[nf][1];
            sb2 += acc[nf][2] + acc[nf][3];
        }
        sa  += __shfl_xor_sync(0xffffffffu, sa, 1);
        sa  += __shfl_xor_sync(0xffffffffu, sa, 2);
        sb2 += __shfl_xor_sync(0xffffffffu, sb2, 1);
        sb2 += __shfl_xor_sync(0xffffffffu, sb2, 2);
        float inva = 1.f / sa, invb = 1.f / sb2;
        #pragma unroll
        for (int nf = 0; nf < 7; nf++) {
            acc[nf][0] *= inva; acc[nf][1] *= inva;
            acc[nf][2] *= invb; acc[nf][3] *= invb;
        }

        uint32_t pah[4][4], pal[4][4];
        #pragma unroll
        for (int kf = 0; kf < 4; kf++) {
            #pragma unroll
            for (int half = 0; half < 2; half++) {
                int nf = 2 * kf + half;
                if (nf < 7) {
                    float p0 = acc[nf][0], p1 = acc[nf][1];
                    float p2 = acc[nf][2], p3 = acc[nf][3];
                    uint32_t h01 = pack_bf2(p0, p1), h23 = pack_bf2(p2, p3);
                    float r0f = p0 - __bfloat162float(__ushort_as_bfloat16((unsigned short)h01));
                    float r1f = p1 - __bfloat162float(__ushort_as_bfloat16((unsigned short)(h01 >> 16)));
                    float r2f = p2 - __bfloat162float(__ushort_as_bfloat16((unsigned short)h23));
                    float r3f = p3 - __bfloat162float(__ushort_as_bfloat16((unsigned short)(h23 >> 16)));
                    pah[kf][half * 2]     = h01;
                    pah[kf][half * 2 + 1] = h23;
                    pal[kf][half * 2]     = pack_bf2(r0f, r1f);
                    pal[kf][half * 2 + 1] = pack_bf2(r2f, r3f);
                } else {
                    pah[kf][half * 2] = 0u; pah[kf][half * 2 + 1] = 0u;
                    pal[kf][half * 2] = 0u; pal[kf][half * 2 + 1] = 0u;
                }
            }
        }

        float oacc[4][4];
        #pragma unroll
        for (int nf = 0; nf < 4; nf++)
            #pragma unroll
            for (int j = 0; j < 4; j++) oacc[nf][j] = 0.f;

        #pragma unroll
        for (int nf = 0; nf < 4; nf++) {
            int dh = nf * 8 + l4;
            #pragma unroll
            for (int kf = 0; kf < 4; kf++) {
                uint32_t bh[2], bl[2];
                bh[0] = *(const uint32_t*)&sVh[dh * 66 + kf * 16 + lm * 2];
                bh[1] = *(const uint32_t*)&sVh[dh * 66 + kf * 16 + lm * 2 + 8];
                bl[0] = *(const uint32_t*)&sVl[dh * 66 + kf * 16 + lm * 2];
                bl[1] = *(const uint32_t*)&sVl[dh * 66 + kf * 16 + lm * 2 + 8];
                mma16816(oacc[nf], pah[kf], bh);
                mma16816(oacc[nf], pal[kf], bh);
                mma16816(oacc[nf], pah[kf], bl);
            }
        }

        if (ra < NTOK) {
            float* orow = g_attn + ((size_t)b * NTOK + ra) * DIM + h * DH;
            #pragma unroll
            for (int nf = 0; nf < 4; nf++)
                *(float2*)(orow + nf * 8 + lm * 2) = make_float2(oacc[nf][0], oacc[nf][1]);
        }
        if (rb < NTOK) {
            float* orow = g_attn + ((size_t)b * NTOK + rb) * DIM + h * DH;
            #pragma unroll
            for (int nf = 0; nf < 4; nf++)
                *(float2*)(orow + nf * 8 + lm * 2) = make_float2(oacc[nf][2], oacc[nf][3]);
        }
    }
}

/* ================= host ================= */
extern "C" void kernel_launch(void* const* d_in, const int* in_sizes, int n_in,
                              void* d_out, int out_size)
{
    const float* x          = (const float*)d_in[0];
    const float* qkv_w      = (const float*)d_in[1];
    const float* qkv_b      = (const float*)d_in[2];
    const float* proj_w     = (const float*)d_in[3];
    const float* proj_b     = (const float*)d_in[4];
    const float* bias_table = (const float*)d_in[5];
    const int*   rel_idx    = (const int*)d_in[6];
    float*       out        = (float*)d_out;

    const int nB = in_sizes[0] / (NTOK * DIM);       /* 4096 */
    const int mt = (nB * NTOK) / 128;                /* 1568 */

    void *p_qkv, *p_attn, *p_wqh, *p_wql, *p_wph, *p_wpl;
    cudaGetSymbolAddress(&p_qkv,  g_qkv);
    cudaGetSymbolAddress(&p_attn, g_attn);
    cudaGetSymbolAddress(&p_wqh,  g_wqh);
    cudaGetSymbolAddress(&p_wql,  g_wql);
    cudaGetSymbolAddress(&p_wph,  g_wph);
    cudaGetSymbolAddress(&p_wpl,  g_wpl);

    cudaFuncSetAttribute(gemm_bf16x3, cudaFuncAttributeMaxDynamicSharedMemorySize, GEMM_SMEM);

    prep_kernel<<<432, 256>>>(qkv_w, proj_w, bias_table, rel_idx);

    gemm_bf16x3<<<mt, 256, GEMM_SMEM>>>(
        x, (const __nv_bfloat16*)p_wqh, (const __nv_bfloat16*)p_wql,
        qkv_b, (float*)p_qkv, 576, 3);

    attn_win<<<nB, 128>>>();

    gemm_bf16x3<<<mt, 256, GEMM_SMEM>>>(
        (const float*)p_attn, (const __nv_bfloat16*)p_wph, (const __nv_bfloat16*)p_wpl,
        proj_b, out, 192, 1);
}